// round 16
// baseline (speedup 1.0000x reference)
#include <cuda_runtime.h>
#include <cuda_fp16.h>
#include <cstdint>

#define S 4096
#define DM 1024
#define H 16
#define HD 64
#define WIN 512
#define NK 3072

// ---------------- device scratch ------------------------------------------
// g_xc : a-frag [k32(32)][mt(256)][k16pair(2)][lane][4]   (stage chunk contiguous)
// g_wc : b-frag [k32(32)][np16(192)][k16pair(2)][lane][4]
// g_q2 : a-frag [h][mt(256)][d16(4)][lane][4]
// g_k2 : b-frag [h][kp16(256)][d16(4)][lane][4]   (8KB per 64-key tile, contiguous)
// g_v2 : b-frag [h][t(64)][dp16(4)][k16(4)][lane][4]
__device__ uint32_t g_xc[S * DM / 2];
__device__ uint32_t g_wc[DM * NK / 2];
__device__ uint32_t g_q2[H * S * HD / 2];
__device__ uint32_t g_k2[H * S * HD / 2];
__device__ uint32_t g_v2[H * S * HD / 2];

// ---------------- helpers ---------------------------------------------------
__device__ __forceinline__ uint32_t h2(float lo, float hi) {
    half2 h = __floats2half2_rn(lo, hi);
    return *(uint32_t*)&h;
}
__device__ __forceinline__ float ex2f(float x) {
    float r;
    asm("ex2.approx.f32 %0, %1;" : "=f"(r) : "f"(x));
    return r;
}
__device__ __forceinline__ uint32_t smem_u32(const void* p) {
    uint32_t a;
    asm("{ .reg .u64 t; cvta.to.shared.u64 t, %1; cvt.u32.u64 %0, t; }"
        : "=r"(a) : "l"(p));
    return a;
}
__device__ __forceinline__ void bulkcp(uint32_t dst, const void* src, uint32_t bytes,
                                       uint32_t mbar) {
    asm volatile(
        "cp.async.bulk.shared::cluster.global.mbarrier::complete_tx::bytes "
        "[%0], [%1], %2, [%3];"
        :: "r"(dst), "l"(src), "r"(bytes), "r"(mbar) : "memory");
}
#define MBAR_INIT(a, c) \
    asm volatile("mbarrier.init.shared.b64 [%0], %1;" :: "r"(a), "r"(c) : "memory")
#define MBAR_EXPECT(a, tx) \
    asm volatile("mbarrier.arrive.expect_tx.shared.b64 _, [%0], %1;" \
                 :: "r"(a), "r"(tx) : "memory")
#define MBAR_WAIT(addr, ph) do {                                               \
    uint32_t _m = (addr); uint32_t _p = (ph); uint32_t _d;                     \
    asm volatile("{ .reg .pred p; mbarrier.try_wait.parity.acquire.cta.shared::cta.b64 p, [%1], %2;" \
                 " selp.b32 %0, 1, 0, p; }" : "=r"(_d) : "r"(_m), "r"(_p) : "memory"); \
    if (!_d) {                                                                 \
        asm volatile("{ .reg .pred P1; WL_%=: mbarrier.try_wait.parity.acquire.cta.shared::cta.b64 P1, [%0], %1, 0x989680;" \
                     " @P1 bra.uni WD_%=; bra.uni WL_%=; WD_%=: }"             \
                     :: "r"(_m), "r"(_p) : "memory");                          \
    } } while (0)

__device__ __forceinline__ void mma16816(float* c, const uint32_t* a,
                                         uint32_t b0, uint32_t b1) {
    asm volatile(
        "mma.sync.aligned.m16n8k16.row.col.f32.f16.f16.f32 "
        "{%0,%1,%2,%3}, {%4,%5,%6,%7}, {%8,%9}, {%0,%1,%2,%3};"
        : "+f"(c[0]), "+f"(c[1]), "+f"(c[2]), "+f"(c[3])
        : "r"(a[0]), "r"(a[1]), "r"(a[2]), "r"(a[3]), "r"(b0), "r"(b1));
}

// ---------------- prep (k-outermost frag layouts) ---------------------------
__global__ __launch_bounds__(256) void prep_x(const float* __restrict__ x) {
    int row = blockIdx.x;
    int k0 = threadIdx.x * 4;
    float4 v = *(const float4*)&x[(size_t)row * DM + k0];
    uint32_t ha = h2(v.x, v.y);
    uint32_t hb = h2(v.z, v.w);
    int base = ((((k0 >> 5) * 256 + (row >> 4)) * 2) + ((k0 >> 4) & 1)) * 128;
    int r = ((row >> 3) & 1) + 2 * ((k0 >> 3) & 1);
    int lane = (row & 7) * 4 + ((k0 & 7) >> 1);
    g_xc[base + lane * 4 + r] = ha;
    g_xc[base + (lane + 1) * 4 + r] = hb;
}
__global__ __launch_bounds__(256) void prep_w(const float* __restrict__ w) {
    int g = blockIdx.x * 256 + threadIdx.x;
    int k0 = 2 * (g / 768);
    int n0 = 4 * (g % 768);
    float4 v0 = *(const float4*)&w[(size_t)k0 * NK + n0];
    float4 v1 = *(const float4*)&w[(size_t)(k0 + 1) * NK + n0];
    float a0[4] = {v0.x, v0.y, v0.z, v0.w};
    float a1[4] = {v1.x, v1.y, v1.z, v1.w};
    int lcp = (k0 & 7) >> 1;
    int reg = (k0 >> 3) & 1;
    int blk0 = ((k0 >> 5) * 192 + (n0 >> 4)) * 2 + ((k0 >> 4) & 1);
#pragma unroll
    for (int t = 0; t < 4; t++) {
        int n = n0 + t;
        g_wc[(size_t)blk0 * 128 + ((n & 7) * 4 + lcp) * 4 + ((n >> 3) & 1) * 2 + reg]
            = h2(a0[t], a1[t]);
    }
}

// ---------------- fp16 KQV GEMM: 128x128, BK=32, TMA-bulk 4 stages ----------
#define GSTAGE_B 16384
#define GNSTAGES 4
#define GEMM_SMEM (GNSTAGES * GSTAGE_B + 64)

__global__ __launch_bounds__(256) void kqv_gemm_mma() {
    extern __shared__ __align__(1024) uint8_t smem_raw[];
    uint32_t sb = smem_u32(smem_raw);
    const int tid = threadIdx.x;
    const int warp = tid >> 5, lane = tid & 31;
    const int lr = lane >> 2, lc = lane & 3;
    const int wm = warp >> 1, wn = warp & 1;
    const int n0 = blockIdx.x * 128;
    const int m0 = blockIdx.y * 128;
    const int mt0 = blockIdx.y * 8;
    const int npb = blockIdx.x * 8;
    const uint32_t mb = sb + GNSTAGES * GSTAGE_B;

    if (tid == 0) {
#pragma unroll
        for (int s = 0; s < GNSTAGES; s++) MBAR_INIT(mb + s * 8, 1);
    }
    __syncthreads();
    if (tid == 0) {
#pragma unroll
        for (int s = 0; s < GNSTAGES - 1; s++) {
            MBAR_EXPECT(mb + s * 8, 16384);
            bulkcp(sb + s * GSTAGE_B,
                   g_xc + (size_t)((s * 256 + mt0) * 2) * 128, 8192, mb + s * 8);
            bulkcp(sb + s * GSTAGE_B + 8192,
                   g_wc + (size_t)((s * 192 + npb) * 2) * 128, 8192, mb + s * 8);
        }
    }

    float c[2][8][4];
#pragma unroll
    for (int i = 0; i < 2; i++)
#pragma unroll
        for (int j = 0; j < 8; j++)
#pragma unroll
            for (int t = 0; t < 4; t++) c[i][j][t] = 0.f;

    for (int kt = 0; kt < 32; kt++) {
        int st = kt & 3;
        MBAR_WAIT(mb + st * 8, (kt >> 2) & 1);
        __syncthreads();
        if (tid == 0) {
            int nk = kt + GNSTAGES - 1;
            if (nk < 32) {
                int ws = nk & 3;
                MBAR_EXPECT(mb + ws * 8, 16384);
                bulkcp(sb + ws * GSTAGE_B,
                       g_xc + (size_t)((nk * 256 + mt0) * 2) * 128, 8192, mb + ws * 8);
                bulkcp(sb + ws * GSTAGE_B + 8192,
                       g_wc + (size_t)((nk * 192 + npb) * 2) * 128, 8192, mb + ws * 8);
            }
        }
        const uint32_t* As = (const uint32_t*)(smem_raw + st * GSTAGE_B);
        const uint32_t* Bs = As + 2048;
        uint32_t a[2][2][4], b[4][2][4];
#pragma unroll
        for (int i = 0; i < 2; i++)
#pragma unroll
            for (int kk = 0; kk < 2; kk++) {
                uint4 v = *(const uint4*)&As[((wm * 2 + i) * 2 + kk) * 128 + lane * 4];
                a[i][kk][0] = v.x; a[i][kk][1] = v.y; a[i][kk][2] = v.z; a[i][kk][3] = v.w;
            }
#pragma unroll
        for (int jp = 0; jp < 4; jp++)
#pragma unroll
            for (int kk = 0; kk < 2; kk++) {
                uint4 v = *(const uint4*)&Bs[((wn * 4 + jp) * 2 + kk) * 128 + lane * 4];
                b[jp][kk][0] = v.x; b[jp][kk][1] = v.y; b[jp][kk][2] = v.z; b[jp][kk][3] = v.w;
            }
#pragma unroll
        for (int kk = 0; kk < 2; kk++)
#pragma unroll
            for (int i = 0; i < 2; i++)
#pragma unroll
                for (int jp = 0; jp < 4; jp++) {
                    mma16816(c[i][2 * jp + 0], a[i][kk], b[jp][kk][0], b[jp][kk][1]);
                    mma16816(c[i][2 * jp + 1], a[i][kk], b[jp][kk][2], b[jp][kk][3]);
                }
    }

    // ---- epilogue (unchanged) ----
    const int gc0 = n0 + wn * 64;
    const int chunk = gc0 >> 10;
    const int h = (gc0 & 1023) >> 6;
    const int mbase = m0 + wm * 32;

#pragma unroll
    for (int i = 0; i < 2; i++) {
#pragma unroll
        for (int j = 0; j < 8; j++) {
            float v0 = c[i][j][0], v1 = c[i][j][1], v2 = c[i][j][2], v3 = c[i][j][3];
            int r = mbase + i * 16 + lr;
            if (chunk == 1) {                     // Q : a-frag
                int base = ((h * 256 + (r >> 4)) * 4 + (j >> 1)) * 128
                           + (lr * 4 + lc) * 4 + 2 * (j & 1);
                g_q2[base + 0] = h2(v0, v1);
                g_q2[base + 1] = h2(v2, v3);
            } else if (chunk == 0) {              // K : pair-packed b-frag
                int base = ((h * 256 + (r >> 4)) * 4 + (j >> 1)) * 128
                           + (lr * 4 + lc) * 4 + (j & 1);
                g_k2[base + 0] = h2(v0, v1);
                g_k2[base + 2] = h2(v2, v3);
            } else {                              // V : pair-packed b-frag
                half* gv = (half*)g_v2;
#pragma unroll
                for (int rb = 0; rb < 2; rb++) {
                    int m = r + rb * 8;
                    float va = rb ? v2 : v0, vb = rb ? v3 : v1;
                    int blkh = (((h * 64 + (m >> 6)) * 4 + (j >> 1)) * 4 + ((m >> 4) & 3)) * 256;
                    int sub = rb * 2 + (lr & 1);
                    int l0 = 8 * lc + (lr >> 1);
                    gv[blkh + (l0 * 4 + (j & 1) * 2) * 2 + sub] = __float2half_rn(va);
                    gv[blkh + ((l0 + 4) * 4 + (j & 1) * 2) * 2 + sub] = __float2half_rn(vb);
                }
            }
        }
    }
}

// ---------------------------------------------------------------------------
// fp16 flash attention, TMA-bulk K/V double buffer.
// ---------------------------------------------------------------------------
#define ASTAGE_B 16384
#define ATTN_SMEM (2 * ASTAGE_B + 32)
#define LOG2E 1.44269504f
#define SCL2 (0.03125f * LOG2E)
#define ONESH2 0x3C003C00u

__global__ __launch_bounds__(128, 4) void attn_tc(float* __restrict__ out) {
    extern __shared__ __align__(1024) uint8_t smem_raw[];
    uint32_t* smu = (uint32_t*)smem_raw;
    uint32_t sb = smem_u32(smem_raw);

    const int tid = threadIdx.x;
    const int w = tid >> 5, lane = tid & 31;
    const int lr = lane >> 2, lc = lane & 3;
    const int qt = blockIdx.x;
    const int h = blockIdx.y;
    const int q0 = qt * 64;
    const uint32_t mb = sb + 2 * ASTAGE_B;

    const float slope2 = exp2f(-0.5f * (float)(h + 1)) * LOG2E;
    const uint32_t* __restrict__ kbh = g_k2 + (size_t)h * 256 * 512;
    const uint32_t* __restrict__ vbh = g_v2 + (size_t)h * 64 * 2048;

    const int kt0 = (qt >= 8) ? (qt - 8) : 0;
    const int kt1 = qt;
    const int nt_total = kt1 - kt0 + 1;

    if (tid == 0) {
        MBAR_INIT(mb + 0, 1);
        MBAR_INIT(mb + 8, 1);
    }
    __syncthreads();
    if (tid == 0) {
        MBAR_EXPECT(mb + 0, 16384);
        bulkcp(sb, kbh + (size_t)kt1 * 2048, 8192, mb + 0);
        bulkcp(sb + 8192, vbh + (size_t)kt1 * 2048, 8192, mb + 0);
    }

    uint32_t qa[4][4];
    {
        const uint32_t* qb = g_q2 + (size_t)((h * 256 + qt * 4 + w) * 4) * 128;
#pragma unroll
        for (int d16 = 0; d16 < 4; d16++) {
            uint4 v = *(const uint4*)&qb[d16 * 128 + lane * 4];
            qa[d16][0] = v.x; qa[d16][1] = v.y; qa[d16][2] = v.z; qa[d16][3] = v.w;
        }
    }

    float o[8][4], oe[4];
    float m0r = -1e30f, m1r = -1e30f;
#pragma unroll
    for (int dt = 0; dt < 8; dt++)
#pragma unroll
        for (int t = 0; t < 4; t++) o[dt][t] = 0.f;
#pragma unroll
    for (int t = 0; t < 4; t++) oe[t] = 0.f;

    const int i0 = q0 + w * 16 + lr;
    const int i1 = i0 + 8;
    const float s8 = slope2 * 8.f;

    for (int it = 0; it < nt_total; it++) {
        const int kt = kt1 - it;                  // descending
        const int st = it & 1;
        MBAR_WAIT(mb + st * 8, (it >> 1) & 1);
        __syncthreads();
        if (tid == 0 && it + 1 < nt_total) {
            uint32_t m2 = mb + (st ^ 1) * 8;
            MBAR_EXPECT(m2, 16384);
            bulkcp(sb + (st ^ 1) * ASTAGE_B, kbh + (size_t)(kt - 1) * 2048, 8192, m2);
            bulkcp(sb + (st ^ 1) * ASTAGE_B + 8192, vbh + (size_t)(kt - 1) * 2048, 8192, m2);
        }

        const uint32_t* Ks = smu + st * (ASTAGE_B / 4);
        const uint32_t* Vs = Ks + 2048;
        const int kb = kt * 64;

        // ---- S = Q K^T ----
        float sc[8][4];
#pragma unroll
        for (int nt = 0; nt < 8; nt++)
#pragma unroll
            for (int t = 0; t < 4; t++) sc[nt][t] = 0.f;
#pragma unroll
        for (int d16 = 0; d16 < 4; d16++) {
#pragma unroll
            for (int np = 0; np < 4; np++) {
                uint4 v = *(const uint4*)&Ks[(np * 4 + d16) * 128 + lane * 4];
                mma16816(sc[2 * np + 0], qa[d16], v.x, v.y);
                mma16816(sc[2 * np + 1], qa[d16], v.z, v.w);
            }
        }

        // ---- bias/mask (log2 domain) + max ----
        const bool full = (kt >= qt - 7) && (kt <= qt - 1);
        float mx0 = -3e38f, mx1 = -3e38f;
        if (full) {
            float bias = slope2 * (float)(kb + 2 * lc - i0);
#pragma unroll
            for (int nt = 0; nt < 8; nt++) {
                sc[nt][0] = fmaf(sc[nt][0], SCL2, bias);
                sc[nt][1] = fmaf(sc[nt][1], SCL2, bias + slope2);
                sc[nt][2] = fmaf(sc[nt][2], SCL2, bias - s8);
                sc[nt][3] = fmaf(sc[nt][3], SCL2, bias - s8 + slope2);
                mx0 = fmaxf(mx0, fmaxf(sc[nt][0], sc[nt][1]));
                mx1 = fmaxf(mx1, fmaxf(sc[nt][2], sc[nt][3]));
                bias += s8;
            }
        } else {
#pragma unroll
            for (int nt = 0; nt < 8; nt++) {
                int j0 = kb + nt * 8 + 2 * lc;
                int d00 = i0 - j0;
                sc[nt][0] = (d00 >= 0 && d00 <= WIN)
                                ? fmaf(sc[nt][0], SCL2, slope2 * (float)(-d00)) : -3e38f;
                int d01 = d00 - 1;
                sc[nt][1] = (d01 >= 0 && d01 <= WIN)
                                ? fmaf(sc[nt][1], SCL2, slope2 * (float)(-d01)) : -3e38f;
                int d10 = i1 - j0;
                sc[nt][2] = (d10 >= 0 && d10 <= WIN)
                                ? fmaf(sc[nt][2], SCL2, slope2 * (float)(-d10)) : -3e38f;
                int d11 = d10 - 1;
                sc[nt][3] = (d11 >= 0 && d11 <= WIN)
                                ? fmaf(sc[nt][3], SCL2, slope2 * (float)(-d11)) : -3e38f;
                mx0 = fmaxf(mx0, fmaxf(sc[nt][0], sc[nt][1]));
                mx1 = fmaxf(mx1, fmaxf(sc[nt][2], sc[nt][3]));
            }
        }
        mx0 = fmaxf(mx0, __shfl_xor_sync(0xffffffffu, mx0, 1));
        mx0 = fmaxf(mx0, __shfl_xor_sync(0xffffffffu, mx0, 2));
        mx1 = fmaxf(mx1, __shfl_xor_sync(0xffffffffu, mx1, 1));
        mx1 = fmaxf(mx1, __shfl_xor_sync(0xffffffffu, mx1, 2));

        float mn0 = fmaxf(m0r, mx0), mn1 = fmaxf(m1r, mx1);
        bool upd = (mn0 > m0r) || (mn1 > m1r);
        if (__any_sync(0xffffffffu, upd)) {
            float al0 = ex2f(m0r - mn0), al1 = ex2f(m1r - mn1);
#pragma unroll
            for (int dt = 0; dt < 8; dt++) {
                o[dt][0] *= al0; o[dt][1] *= al0;
                o[dt][2] *= al1; o[dt][3] *= al1;
            }
            oe[0] *= al0; oe[1] *= al0;
            oe[2] *= al1; oe[3] *= al1;
        }
        m0r = mn0; m1r = mn1;

        // ---- p = exp2(sc - mn), in-register a-frags ----
        uint32_t pa[4][4];
#pragma unroll
        for (int nt = 0; nt < 8; nt++) {
            float p00 = ex2f(sc[nt][0] - mn0);
            float p01 = ex2f(sc[nt][1] - mn0);
            float p10 = ex2f(sc[nt][2] - mn1);
            float p11 = ex2f(sc[nt][3] - mn1);
            pa[nt >> 1][(nt & 1) * 2 + 0] = h2(p00, p01);
            pa[nt >> 1][(nt & 1) * 2 + 1] = h2(p10, p11);
        }

        // ---- O += P V (+ ones column row sums into oe) ----
#pragma unroll
        for (int k16 = 0; k16 < 4; k16++) {
#pragma unroll
            for (int dp = 0; dp < 4; dp++) {
                uint4 v = *(const uint4*)&Vs[(dp * 4 + k16) * 128 + lane * 4];
                mma16816(o[2 * dp + 0], pa[k16], v.x, v.y);
                mma16816(o[2 * dp + 1], pa[k16], v.z, v.w);
            }
            mma16816(oe, pa[k16], ONESH2, ONESH2);
        }
    }

    // ---- normalize + write ----
    float inv0 = 1.f / oe[0], inv1 = 1.f / oe[2];
    float* o0 = out + (size_t)i0 * DM + h * HD;
    float* o1 = out + (size_t)i1 * DM + h * HD;
#pragma unroll
    for (int dt = 0; dt < 8; dt++) {
        *(float2*)&o0[dt * 8 + 2 * lc] = make_float2(o[dt][0] * inv0, o[dt][1] * inv0);
        *(float2*)&o1[dt * 8 + 2 * lc] = make_float2(o[dt][2] * inv1, o[dt][3] * inv1);
    }
}

// ---------------------------------------------------------------------------
extern "C" void kernel_launch(void* const* d_in, const int* in_sizes, int n_in,
                              void* d_out, int out_size) {
    const float* x = (const float*)d_in[0];
    const float* w = (const float*)d_in[1];
    if (n_in >= 2 && in_sizes[0] == DM * NK && in_sizes[1] == S * DM) {
        const float* t = x; x = w; w = t;
    }
    float* out = (float*)d_out;

    static int attr_set = 0;
    if (!attr_set) {
        cudaFuncSetAttribute(kqv_gemm_mma, cudaFuncAttributeMaxDynamicSharedMemorySize,
                             GEMM_SMEM);
        cudaFuncSetAttribute(attn_tc, cudaFuncAttributeMaxDynamicSharedMemorySize,
                             ATTN_SMEM);
        attr_set = 1;
    }

    prep_x<<<4096, 256>>>(x);
    prep_w<<<1536, 256>>>(w);

    dim3 ggrid(NK / 128, S / 128);
    kqv_gemm_mma<<<ggrid, 256, GEMM_SMEM>>>();

    dim3 agrid(S / 64, H);
    attn_tc<<<agrid, 128, ATTN_SMEM>>>(out);
}